// round 1
// baseline (speedup 1.0000x reference)
#include <cuda_runtime.h>

// ---------------- problem constants ----------------
#define B_     2
#define S_     2048
#define H_     2048
#define NH_    16
#define HD_    128
#define CACHE_ 2048
#define KV_    4096           // CACHE_ + S_
#define M_     4096           // B_*S_
#define KDIM_  2048           // H_

#define SCALE_ 0.08838834764831845f   // 1/sqrt(128)

// scratch (allocation-free rule: __device__ globals)
static __device__ float g_q[(size_t)M_ * H_];     // q as [B,NH,S,HD]
static __device__ float g_attn[(size_t)M_ * H_];  // attn out as [B,S,H]

typedef unsigned long long u64;

// ---------------- f32x2 helpers (Blackwell packed fp32) ----------------
__device__ __forceinline__ void ffma2(u64 &acc, u64 a, u64 b) {
    asm("fma.rn.f32x2 %0, %1, %2, %0;" : "+l"(acc) : "l"(a), "l"(b));
}
__device__ __forceinline__ u64 fmul2(u64 a, u64 b) {
    u64 r; asm("mul.rn.f32x2 %0, %1, %2;" : "=l"(r) : "l"(a), "l"(b)); return r;
}
__device__ __forceinline__ u64 pack2(float x, float y) {
    u64 r; asm("mov.b64 %0, {%1, %2};" : "=l"(r) : "f"(x), "f"(y)); return r;
}
__device__ __forceinline__ float2 unpack2(u64 v) {
    float2 r; asm("mov.b64 {%0, %1}, %2;" : "=f"(r.x), "=f"(r.y) : "l"(v)); return r;
}

union F4 { float4 f; float s[4]; u64 u[2]; };

// ---------------- cache splice: k_cache/v_cache -> out rows [0,CACHE) ----------------
__global__ void copy_cache_kernel(const float4* __restrict__ kc,
                                  const float4* __restrict__ vc,
                                  float4* __restrict__ ko,
                                  float4* __restrict__ vo) {
    int i = blockIdx.x * blockDim.x + threadIdx.x;     // 0 .. B_*NH_*CACHE_*HD_/4 - 1 (=2097152)
    int chunk = i >> 16;                               // per (b,h): CACHE_*HD_/4 = 65536
    int rem   = i & 65535;
    size_t d = (size_t)chunk * (KV_ * HD_ / 4) + rem;  // dst chunk stride: 131072
    ko[d] = kc[i];
    vo[d] = vc[i];
}

// ---------------- generic NT GEMM: C[M,N] = X[M,K] * W[N,K]^T + bias ----------------
// tile 128x64x16, 256 threads, per-thread 8x4 via f32x2 (pairs along m).
// kind==0: dst[row*H_ + j]
// kind==1: dst[((b*NH_ + j/HD_)*Lrow + off + s)*HD_ + j%HD_]  with row = b*S_ + s
__global__ __launch_bounds__(256)
void gemm_nt(const float* __restrict__ X, const float* __restrict__ W,
             const float* __restrict__ bias, float* __restrict__ dst,
             int kind, int Lrow, int off)
{
    __shared__ float As[16][132];   // transposed A:  As[k][m]
    __shared__ float Bs[16][140];   // duplicated B:  Bs[k][2n]=Bs[k][2n+1]=W[n][k]

    const int tid = threadIdx.x;
    const int tx  = tid & 15, ty = tid >> 4;
    const int m0  = blockIdx.y * 128, n0 = blockIdx.x * 64;
    const int lrow = tid >> 2, lc4 = tid & 3;

    u64 c2[4][4];
    #pragma unroll
    for (int i = 0; i < 4; i++)
        #pragma unroll
        for (int j = 0; j < 4; j++) c2[i][j] = 0ULL;

    const float* Ap0 = X + (size_t)(m0 + lrow) * KDIM_ + lc4 * 4;
    const float* Ap1 = Ap0 + (size_t)64 * KDIM_;
    const float* Bp  = W + (size_t)(n0 + lrow) * KDIM_ + lc4 * 4;

    for (int k0 = 0; k0 < KDIM_; k0 += 16) {
        __syncthreads();
        float4 a0 = *(const float4*)(Ap0 + k0);
        float4 a1 = *(const float4*)(Ap1 + k0);
        float4 bv = *(const float4*)(Bp + k0);
        As[lc4*4+0][lrow]    = a0.x; As[lc4*4+1][lrow]    = a0.y;
        As[lc4*4+2][lrow]    = a0.z; As[lc4*4+3][lrow]    = a0.w;
        As[lc4*4+0][lrow+64] = a1.x; As[lc4*4+1][lrow+64] = a1.y;
        As[lc4*4+2][lrow+64] = a1.z; As[lc4*4+3][lrow+64] = a1.w;
        *(float2*)&Bs[lc4*4+0][2*lrow] = make_float2(bv.x, bv.x);
        *(float2*)&Bs[lc4*4+1][2*lrow] = make_float2(bv.y, bv.y);
        *(float2*)&Bs[lc4*4+2][2*lrow] = make_float2(bv.z, bv.z);
        *(float2*)&Bs[lc4*4+3][2*lrow] = make_float2(bv.w, bv.w);
        __syncthreads();

        #pragma unroll
        for (int kk = 0; kk < 16; kk++) {
            F4 qa0, qa1, qb0, qb1;
            qa0.f = *(const float4*)&As[kk][ty*8];
            qa1.f = *(const float4*)&As[kk][ty*8+4];
            qb0.f = *(const float4*)&Bs[kk][tx*8];
            qb1.f = *(const float4*)&Bs[kk][tx*8+4];
            #pragma unroll
            for (int n = 0; n < 4; n++) {
                u64 bb = (n < 2) ? qb0.u[n] : qb1.u[n-2];
                ffma2(c2[0][n], qa0.u[0], bb);
                ffma2(c2[1][n], qa0.u[1], bb);
                ffma2(c2[2][n], qa1.u[0], bb);
                ffma2(c2[3][n], qa1.u[1], bb);
            }
        }
    }

    // epilogue
    float4 bb4 = *(const float4*)(bias + n0 + tx*4);
    #pragma unroll
    for (int mp = 0; mp < 4; mp++) {
        float2 u0 = unpack2(c2[mp][0]);
        float2 u1 = unpack2(c2[mp][1]);
        float2 u2 = unpack2(c2[mp][2]);
        float2 u3 = unpack2(c2[mp][3]);
        float4 lo = make_float4(u0.x+bb4.x, u1.x+bb4.y, u2.x+bb4.z, u3.x+bb4.w);
        float4 hi = make_float4(u0.y+bb4.x, u1.y+bb4.y, u2.y+bb4.z, u3.y+bb4.w);
        int r0 = m0 + ty*8 + mp*2;
        int j0 = n0 + tx*4;
        float *p0, *p1;
        if (kind == 0) {
            p0 = dst + (size_t)r0 * H_ + j0;
            p1 = p0 + H_;
        } else {
            int bb_ = r0 >> 11;           // /S_
            int s   = r0 & (S_ - 1);
            int hh  = j0 >> 7;            // /HD_
            int d   = j0 & (HD_ - 1);
            p0 = dst + ((size_t)(bb_*NH_ + hh) * Lrow + off + s) * HD_ + d;
            p1 = p0 + HD_;                // next s (never crosses a batch: 128-row tiles)
        }
        *(float4*)p0 = lo;
        *(float4*)p1 = hi;
    }
}

// ---------------- flash attention, fp32, 64x64 tiles ----------------
// grid (S_/64, NH_, B_), 256 threads, dynamic smem 100352B
#define ATTN_SMEM ((64*132*2 + 64*128) * 4)

__global__ __launch_bounds__(256, 2)
void attn_kernel(const float* __restrict__ Q,    // [B,NH,S,HD]
                 const float* __restrict__ Kf,   // [B,NH,KV,HD]
                 const float* __restrict__ Vf,   // [B,NH,KV,HD]
                 const float* __restrict__ Msk,  // [B,1,S,KV]
                 float* __restrict__ Out)        // [B,S,H]
{
    extern __shared__ float sm[];
    float* Qs = sm;               // [64][132]
    float* Ks = sm + 64*132;      // [64][132]; reused as Ps[64][68] after scores
    float* Vs = sm + 2*64*132;    // [64][128]
    float* Ps = Ks;

    const int tid = threadIdx.x;
    const int tx = tid & 15, ty = tid >> 4;
    const int qt = blockIdx.x, h = blockIdx.y, b = blockIdx.z;

    const float* Qb = Q + ((size_t)(b*NH_ + h) * S_ + qt*64) * HD_;
    const float* Kb = Kf + (size_t)(b*NH_ + h) * KV_ * HD_;
    const float* Vb = Vf + (size_t)(b*NH_ + h) * KV_ * HD_;
    const float* Mb = Msk + ((size_t)b * S_ + qt*64) * KV_;

    // load Q tile (row-major, padded stride 132)
    #pragma unroll
    for (int it = 0; it < 8; ++it) {
        int f = tid + it*256; int r = f >> 5, c = f & 31;
        *(float4*)(Qs + r*132 + c*4) = *(const float4*)(Qb + (size_t)r*HD_ + c*4);
    }

    u64 o2[4][4];
    float mrow[4], lrow[4];
    #pragma unroll
    for (int i = 0; i < 4; i++) {
        mrow[i] = -1e30f; lrow[i] = 0.f;
        #pragma unroll
        for (int j = 0; j < 4; j++) o2[i][j] = 0ULL;
    }

    for (int t = 0; t < KV_/64; ++t) {
        __syncthreads();   // previous PV done reading Ps/Vs (also covers Q load at t=0)
        const float* Kt = Kb + (size_t)t*64*HD_;
        const float* Vt = Vb + (size_t)t*64*HD_;
        #pragma unroll
        for (int it = 0; it < 8; ++it) {
            int f = tid + it*256; int r = f >> 5, c = f & 31;
            *(float4*)(Ks + r*132 + c*4) = *(const float4*)(Kt + (size_t)r*HD_ + c*4);
            *(float4*)(Vs + r*128 + c*4) = *(const float4*)(Vt + (size_t)r*HD_ + c*4);
        }
        __syncthreads();

        // ---- scores: acc[m][j] accumulates (even-d, odd-d) partial dots ----
        u64 acc[4][4];
        #pragma unroll
        for (int i = 0; i < 4; i++)
            #pragma unroll
            for (int j = 0; j < 4; j++) acc[i][j] = 0ULL;

        #pragma unroll 8
        for (int d = 0; d < HD_; d += 4) {
            F4 q4[4], k4[4];
            #pragma unroll
            for (int mm = 0; mm < 4; mm++)
                q4[mm].f = *(const float4*)(Qs + (ty*4+mm)*132 + d);
            #pragma unroll
            for (int jj = 0; jj < 4; jj++)
                k4[jj].f = *(const float4*)(Ks + (tx + 16*jj)*132 + d);
            #pragma unroll
            for (int mm = 0; mm < 4; mm++)
                #pragma unroll
                for (int jj = 0; jj < 4; jj++) {
                    ffma2(acc[mm][jj], q4[mm].u[0], k4[jj].u[0]);
                    ffma2(acc[mm][jj], q4[mm].u[1], k4[jj].u[1]);
                }
        }

        // ---- online softmax update ----
        float p[4][4];
        const int kbase = t*64 + tx;
        #pragma unroll
        for (int mm = 0; mm < 4; mm++) {
            const int qrow = ty*4 + mm;
            const float* mp_ = Mb + (size_t)qrow * KV_ + kbase;
            float sv[4];
            float smax = -1e30f;
            #pragma unroll
            for (int jj = 0; jj < 4; jj++) {
                float2 u = unpack2(acc[mm][jj]);
                float s = (u.x + u.y) * SCALE_ + mp_[16*jj];
                sv[jj] = s;
                smax = fmaxf(smax, s);
            }
            #pragma unroll
            for (int o = 8; o; o >>= 1)
                smax = fmaxf(smax, __shfl_xor_sync(0xffffffffu, smax, o));
            float newm = fmaxf(mrow[mm], smax);
            float alpha = __expf(mrow[mm] - newm);
            float rsum = 0.f;
            #pragma unroll
            for (int jj = 0; jj < 4; jj++) {
                float e = __expf(sv[jj] - newm);
                p[mm][jj] = e;
                rsum += e;
            }
            #pragma unroll
            for (int o = 8; o; o >>= 1)
                rsum += __shfl_xor_sync(0xffffffffu, rsum, o);
            lrow[mm] = lrow[mm]*alpha + rsum;
            mrow[mm] = newm;
            u64 a2 = pack2(alpha, alpha);
            #pragma unroll
            for (int jj = 0; jj < 4; jj++) o2[mm][jj] = fmul2(o2[mm][jj], a2);
        }

        __syncthreads();   // all threads done reading Ks before overwriting as Ps
        #pragma unroll
        for (int mm = 0; mm < 4; mm++)
            #pragma unroll
            for (int jj = 0; jj < 4; jj++)
                Ps[(ty*4+mm)*68 + tx + 16*jj] = p[mm][jj];
        __syncthreads();

        // ---- PV: O[m][d] += P[m][n] * V[n][d], pairs along d ----
        #pragma unroll 4
        for (int n = 0; n < 64; ++n) {
            F4 v0, v1;
            v0.f = *(const float4*)(Vs + n*128 + tx*8);
            v1.f = *(const float4*)(Vs + n*128 + tx*8 + 4);
            #pragma unroll
            for (int mm = 0; mm < 4; mm++) {
                float pv = Ps[(ty*4+mm)*68 + n];
                u64 pp = pack2(pv, pv);
                ffma2(o2[mm][0], pp, v0.u[0]);
                ffma2(o2[mm][1], pp, v0.u[1]);
                ffma2(o2[mm][2], pp, v1.u[0]);
                ffma2(o2[mm][3], pp, v1.u[1]);
            }
        }
    }

    // epilogue: O / l -> g_attn[b, s, h*HD + d]
    #pragma unroll
    for (int mm = 0; mm < 4; mm++) {
        float inv = 1.0f / lrow[mm];
        int qrow = qt*64 + ty*4 + mm;
        float* dstp = Out + ((size_t)b * S_ + qrow) * H_ + h*HD_ + tx*8;
        float2 r0 = unpack2(o2[mm][0]);
        float2 r1 = unpack2(o2[mm][1]);
        float2 r2 = unpack2(o2[mm][2]);
        float2 r3 = unpack2(o2[mm][3]);
        float4 w0 = make_float4(r0.x*inv, r0.y*inv, r1.x*inv, r1.y*inv);
        float4 w1 = make_float4(r2.x*inv, r2.y*inv, r3.x*inv, r3.y*inv);
        *(float4*)dstp       = w0;
        *(float4*)(dstp + 4) = w1;
    }
}

// ---------------- launch ----------------
extern "C" void kernel_launch(void* const* d_in, const int* in_sizes, int n_in,
                              void* d_out, int out_size) {
    (void)in_sizes; (void)n_in; (void)out_size;
    const float* x   = (const float*)d_in[0];
    const float* msk = (const float*)d_in[1];
    const float* kc  = (const float*)d_in[2];
    const float* vc  = (const float*)d_in[3];
    const float* Wq  = (const float*)d_in[4];
    const float* bq  = (const float*)d_in[5];
    const float* Wk  = (const float*)d_in[6];
    const float* bk  = (const float*)d_in[7];
    const float* Wv  = (const float*)d_in[8];
    const float* bv  = (const float*)d_in[9];
    const float* Wo  = (const float*)d_in[10];
    const float* bo  = (const float*)d_in[11];

    float* out = (float*)d_out;                          // [B,S,H]
    float* ko  = out + (size_t)B_ * S_ * H_;             // [B,NH,KV,HD]
    float* vo  = ko  + (size_t)B_ * NH_ * KV_ * HD_;     // [B,NH,KV,HD]

    float *gq = nullptr, *gattn = nullptr;
    cudaGetSymbolAddress((void**)&gq, g_q);
    cudaGetSymbolAddress((void**)&gattn, g_attn);

    cudaFuncSetAttribute(attn_kernel,
                         cudaFuncAttributeMaxDynamicSharedMemorySize, ATTN_SMEM);

    // 1. splice caches into output k/v
    copy_cache_kernel<<<8192, 256>>>((const float4*)kc, (const float4*)vc,
                                     (float4*)ko, (float4*)vo);

    // 2. projections
    dim3 ggrid(H_/64, M_/128);   // (32, 32)
    gemm_nt<<<ggrid, 256>>>(x, Wq, bq, gq, 1, S_,  0);
    gemm_nt<<<ggrid, 256>>>(x, Wk, bk, ko, 1, KV_, CACHE_);
    gemm_nt<<<ggrid, 256>>>(x, Wv, bv, vo, 1, KV_, CACHE_);

    // 3. attention
    attn_kernel<<<dim3(S_/64, NH_, B_), 256, ATTN_SMEM>>>(gq, ko, vo, msk, gattn);

    // 4. output projection
    gemm_nt<<<ggrid, 256>>>(gattn, Wo, bo, out, 0, 0, 0);
}

// round 3
// speedup vs baseline: 1.7029x; 1.7029x over previous
#include <cuda_runtime.h>
#include <cuda_bf16.h>
#include <cstdint>

// ---------------- problem constants ----------------
#define B_     2
#define S_     2048
#define H_     2048
#define NH_    16
#define HD_    128
#define CACHE_ 2048
#define KV_    4096           // CACHE_ + S_
#define M_     4096           // B_*S_
#define KDIM_  2048           // H_

#define SCALE_ 0.08838834764831845f   // 1/sqrt(128)

// scratch (allocation-free rule: __device__ globals)
static __device__ float g_q[(size_t)M_ * H_];     // q as [B,NH,S,HD]
static __device__ float g_attn[(size_t)M_ * H_];  // attn out as [B,S,H]

// bf16 split scratch
static __device__ __nv_bfloat16 sXh[(size_t)M_ * KDIM_];
static __device__ __nv_bfloat16 sXl[(size_t)M_ * KDIM_];
static __device__ __nv_bfloat16 sWqh[(size_t)H_ * KDIM_];
static __device__ __nv_bfloat16 sWql[(size_t)H_ * KDIM_];
static __device__ __nv_bfloat16 sWkh[(size_t)H_ * KDIM_];
static __device__ __nv_bfloat16 sWkl[(size_t)H_ * KDIM_];
static __device__ __nv_bfloat16 sWvh[(size_t)H_ * KDIM_];
static __device__ __nv_bfloat16 sWvl[(size_t)H_ * KDIM_];
static __device__ __nv_bfloat16 sWoh[(size_t)H_ * KDIM_];
static __device__ __nv_bfloat16 sWol[(size_t)H_ * KDIM_];

typedef unsigned long long u64;

// ---------------- helpers ----------------
__device__ __forceinline__ uint32_t smem_u32(const void* p) {
    uint32_t a;
    asm("{ .reg .u64 t; cvta.to.shared.u64 t, %1; cvt.u32.u64 %0, t; }" : "=r"(a) : "l"(p));
    return a;
}

#define LDSM4(r0,r1,r2,r3,addr) \
    asm volatile("ldmatrix.sync.aligned.m8n8.x4.shared.b16 {%0,%1,%2,%3}, [%4];" \
        : "=r"(r0),"=r"(r1),"=r"(r2),"=r"(r3) : "r"(addr))

#define MMA16816(c, a, b) \
    asm volatile("mma.sync.aligned.m16n8k16.row.col.f32.bf16.bf16.f32 " \
        "{%0,%1,%2,%3}, {%4,%5,%6,%7}, {%8,%9}, {%0,%1,%2,%3};" \
        : "+f"((c)[0]),"+f"((c)[1]),"+f"((c)[2]),"+f"((c)[3]) \
        : "r"((a)[0]),"r"((a)[1]),"r"((a)[2]),"r"((a)[3]), "r"((b)[0]),"r"((b)[1]))

#define CP_ASYNC16(saddr, gaddr) \
    asm volatile("cp.async.cg.shared.global [%0], [%1], 16;" :: "r"(saddr), "l"(gaddr))
#define CP_COMMIT() asm volatile("cp.async.commit_group;" ::: "memory")
#define CP_WAIT0()  asm volatile("cp.async.wait_group 0;" ::: "memory")

// f32x2 (Blackwell packed fp32 — baseline PTX, compiled fine in R1)
__device__ __forceinline__ void ffma2(u64 &acc, u64 a, u64 b) {
    asm("fma.rn.f32x2 %0, %1, %2, %0;" : "+l"(acc) : "l"(a), "l"(b));
}
__device__ __forceinline__ u64 fmul2(u64 a, u64 b) {
    u64 r; asm("mul.rn.f32x2 %0, %1, %2;" : "=l"(r) : "l"(a), "l"(b)); return r;
}
__device__ __forceinline__ u64 pack2(float x, float y) {
    u64 r; asm("mov.b64 %0, {%1, %2};" : "=l"(r) : "f"(x), "f"(y)); return r;
}
__device__ __forceinline__ float2 unpack2(u64 v) {
    float2 r; asm("mov.b64 {%0, %1}, %2;" : "=f"(r.x), "=f"(r.y) : "l"(v)); return r;
}
union F4 { float4 f; float s[4]; u64 u[2]; };

// ---------------- cache splice ----------------
__global__ void copy_cache_kernel(const float4* __restrict__ kc,
                                  const float4* __restrict__ vc,
                                  float4* __restrict__ ko,
                                  float4* __restrict__ vo) {
    int i = blockIdx.x * blockDim.x + threadIdx.x;
    int chunk = i >> 16;
    int rem   = i & 65535;
    size_t d = (size_t)chunk * (KV_ * HD_ / 4) + rem;
    ko[d] = kc[i];
    vo[d] = vc[i];
}

// ---------------- fp32 -> bf16 hi/lo split ----------------
union BF4 { __nv_bfloat16 b[4]; uint2 u; };

__global__ void split_kernel(const float4* __restrict__ src,
                             uint2* __restrict__ hi, uint2* __restrict__ lo) {
    int i = blockIdx.x * blockDim.x + threadIdx.x;
    float4 v = src[i];
    BF4 H, L;
    float f[4] = {v.x, v.y, v.z, v.w};
    #pragma unroll
    for (int j = 0; j < 4; j++) {
        __nv_bfloat16 h = __float2bfloat16_rn(f[j]);
        H.b[j] = h;
        L.b[j] = __float2bfloat16_rn(f[j] - __bfloat162float(h));
    }
    hi[i] = H.u;
    lo[i] = L.u;
}

// ---------------- mma.sync bf16-split GEMM ----------------
// C[128x128/CTA] = (Ah+Al)[M,K] x (Bh+Bl)[N,K]^T + bias, fp32 acc
// 3-term: Ah*Bh + Ah*Bl + Al*Bh
// kind==0: dst[row*H_ + col]; kind==1: KV/Q scatter layout
#define GKC      32                   // K per chunk
#define GNCH     (KDIM_/GKC)          // 64 chunks
#define TPAD     40                   // padded row length (bf16 elems)
#define TILE_B   (128*TPAD*2)         // 10240 bytes per tile
#define BUF_B    (4*TILE_B)           // Ah,Al,Bh,Bl
#define GT_SMEM  (512 + 2*BUF_B)      // 82432

__global__ __launch_bounds__(256, 1)
void gemm_mma(const __nv_bfloat16* __restrict__ Ah, const __nv_bfloat16* __restrict__ Al,
              const __nv_bfloat16* __restrict__ Bh, const __nv_bfloat16* __restrict__ Bl,
              const float* __restrict__ bias, float* __restrict__ dst,
              int kind, int Lrow, int off)
{
    extern __shared__ char smc[];
    float* s_bias = (float*)smc;
    const uint32_t sbase = smem_u32(smc + 512);

    const int tid = threadIdx.x;
    const int wid = tid >> 5, lane = tid & 31;
    const int wm = (wid & 3) * 32, wn = (wid >> 2) * 64;
    const int n0 = blockIdx.x * 128, m0 = blockIdx.y * 128;

    if (tid < 128) s_bias[tid] = bias[n0 + tid];

    const __nv_bfloat16* tsrc[4] = {
        Ah + (size_t)m0 * KDIM_, Al + (size_t)m0 * KDIM_,
        Bh + (size_t)n0 * KDIM_, Bl + (size_t)n0 * KDIM_
    };

    // per-thread cp.async source/dest geometry (8 x 16B per chunk)
    const int ld_row = tid >> 2;          // 0..63  (x2 via +64)
    const int ld_c16 = tid & 3;           // 16B column
    // ldmatrix lane geometry
    const int aRow = wm + (lane & 15);
    const uint32_t offA0 = ((uint32_t)(aRow * TPAD + ((lane >> 4) << 3))) * 2u;
    const int bRow = wn + ((lane >> 4) << 3) + (lane & 7);
    const uint32_t offB0 = ((uint32_t)(bRow * TPAD + (((lane >> 3) & 1) << 3))) * 2u;

    float acc[2][8][4];
    #pragma unroll
    for (int i = 0; i < 2; i++)
        #pragma unroll
        for (int j = 0; j < 8; j++)
            #pragma unroll
            for (int q = 0; q < 4; q++) acc[i][j][q] = 0.f;

    // prefetch chunk 0
    {
        uint32_t sb = sbase;
        #pragma unroll
        for (int t = 0; t < 4; t++) {
            const __nv_bfloat16* src = tsrc[t];
            #pragma unroll
            for (int i = 0; i < 2; i++) {
                int row = ld_row + i * 64;
                uint32_t sa = sb + t * TILE_B + (uint32_t)(row * TPAD + ld_c16 * 8) * 2u;
                const void* ga = src + (size_t)row * KDIM_ + ld_c16 * 8;
                CP_ASYNC16(sa, ga);
            }
        }
        CP_COMMIT();
    }

    for (int c = 0; c < GNCH; ++c) {
        CP_WAIT0();
        __syncthreads();
        if (c + 1 < GNCH) {
            uint32_t sb = sbase + ((c + 1) & 1) * BUF_B;
            const int c0 = (c + 1) * GKC;
            #pragma unroll
            for (int t = 0; t < 4; t++) {
                const __nv_bfloat16* src = tsrc[t] + c0;
                #pragma unroll
                for (int i = 0; i < 2; i++) {
                    int row = ld_row + i * 64;
                    uint32_t sa = sb + t * TILE_B + (uint32_t)(row * TPAD + ld_c16 * 8) * 2u;
                    const void* ga = src + (size_t)row * KDIM_ + ld_c16 * 8;
                    CP_ASYNC16(sa, ga);
                }
            }
            CP_COMMIT();
        }

        // compute on buffer c&1
        const uint32_t bb = sbase + (c & 1) * BUF_B;
        #pragma unroll
        for (int ks = 0; ks < 2; ++ks) {
            const uint32_t ko_ = ks * 32;   // 16 bf16 = 32 bytes
            uint32_t ah[2][4], al[2][4];
            #pragma unroll
            for (int mt = 0; mt < 2; ++mt) {
                LDSM4(ah[mt][0], ah[mt][1], ah[mt][2], ah[mt][3],
                      bb + 0 * TILE_B + offA0 + mt * (16 * TPAD * 2) + ko_);
                LDSM4(al[mt][0], al[mt][1], al[mt][2], al[mt][3],
                      bb + 1 * TILE_B + offA0 + mt * (16 * TPAD * 2) + ko_);
            }
            uint32_t bh[8][2], bl[8][2];
            #pragma unroll
            for (int p = 0; p < 4; ++p) {
                uint32_t r0, r1, r2, r3;
                LDSM4(r0, r1, r2, r3,
                      bb + 2 * TILE_B + offB0 + p * (16 * TPAD * 2) + ko_);
                bh[2*p][0] = r0; bh[2*p][1] = r1; bh[2*p+1][0] = r2; bh[2*p+1][1] = r3;
                LDSM4(r0, r1, r2, r3,
                      bb + 3 * TILE_B + offB0 + p * (16 * TPAD * 2) + ko_);
                bl[2*p][0] = r0; bl[2*p][1] = r1; bl[2*p+1][0] = r2; bl[2*p+1][1] = r3;
            }
            #pragma unroll
            for (int mt = 0; mt < 2; ++mt)
                #pragma unroll
                for (int nt = 0; nt < 8; ++nt) {
                    MMA16816(acc[mt][nt], ah[mt], bh[nt]);
                    MMA16816(acc[mt][nt], ah[mt], bl[nt]);
                    MMA16816(acc[mt][nt], al[mt], bh[nt]);
                }
        }
    }
    __syncthreads();

    // epilogue
    #pragma unroll
    for (int mt = 0; mt < 2; ++mt) {
        #pragma unroll
        for (int nt = 0; nt < 8; ++nt) {
            float* cc = acc[mt][nt];
            int row0 = m0 + wm + mt * 16 + (lane >> 2);
            int col  = wn + nt * 8 + (lane & 3) * 2;    // local col in [0,128)
            float2 v0 = make_float2(cc[0] + s_bias[col], cc[1] + s_bias[col + 1]);
            float2 v1 = make_float2(cc[2] + s_bias[col], cc[3] + s_bias[col + 1]);
            float *p0, *p1;
            if (kind == 0) {
                p0 = dst + (size_t)row0 * H_ + n0 + col;
                p1 = p0 + (size_t)8 * H_;
            } else {
                int bb_ = row0 >> 11, s = row0 & (S_ - 1);
                int head = n0 >> 7;
                p0 = dst + ((size_t)(bb_ * NH_ + head) * Lrow + off + s) * HD_ + col;
                p1 = p0 + (size_t)8 * HD_;   // row0+8 stays in same batch (128-row tiles)
            }
            *(float2*)p0 = v0;
            *(float2*)p1 = v1;
        }
    }
}

// ---------------- flash attention, fp32, 64x64 tiles (R1-proven) ----------------
#define ATTN_SMEM ((64*132*2 + 64*128) * 4)

__global__ __launch_bounds__(256, 2)
void attn_kernel(const float* __restrict__ Q,
                 const float* __restrict__ Kf,
                 const float* __restrict__ Vf,
                 const float* __restrict__ Msk,
                 float* __restrict__ Out)
{
    extern __shared__ float smf[];
    float* Qs = smf;
    float* Ks = smf + 64*132;
    float* Vs = smf + 2*64*132;
    float* Ps = Ks;

    const int tid = threadIdx.x;
    const int tx = tid & 15, ty = tid >> 4;
    const int qt = blockIdx.x, h = blockIdx.y, b = blockIdx.z;

    const float* Qb = Q + ((size_t)(b*NH_ + h) * S_ + qt*64) * HD_;
    const float* Kb = Kf + (size_t)(b*NH_ + h) * KV_ * HD_;
    const float* Vb = Vf + (size_t)(b*NH_ + h) * KV_ * HD_;
    const float* Mb = Msk + ((size_t)b * S_ + qt*64) * KV_;

    #pragma unroll
    for (int it = 0; it < 8; ++it) {
        int f = tid + it*256; int r = f >> 5, c = f & 31;
        *(float4*)(Qs + r*132 + c*4) = *(const float4*)(Qb + (size_t)r*HD_ + c*4);
    }

    u64 o2[4][4];
    float mrow[4], lrow[4];
    #pragma unroll
    for (int i = 0; i < 4; i++) {
        mrow[i] = -1e30f; lrow[i] = 0.f;
        #pragma unroll
        for (int j = 0; j < 4; j++) o2[i][j] = 0ULL;
    }

    for (int t = 0; t < KV_/64; ++t) {
        __syncthreads();
        const float* Kt = Kb + (size_t)t*64*HD_;
        const float* Vt = Vb + (size_t)t*64*HD_;
        #pragma unroll
        for (int it = 0; it < 8; ++it) {
            int f = tid + it*256; int r = f >> 5, c = f & 31;
            *(float4*)(Ks + r*132 + c*4) = *(const float4*)(Kt + (size_t)r*HD_ + c*4);
            *(float4*)(Vs + r*128 + c*4) = *(const float4*)(Vt + (size_t)r*HD_ + c*4);
        }
        __syncthreads();

        u64 acc[4][4];
        #pragma unroll
        for (int i = 0; i < 4; i++)
            #pragma unroll
            for (int j = 0; j < 4; j++) acc[i][j] = 0ULL;

        #pragma unroll 8
        for (int d = 0; d < HD_; d += 4) {
            F4 q4[4], k4[4];
            #pragma unroll
            for (int mm = 0; mm < 4; mm++)
                q4[mm].f = *(const float4*)(Qs + (ty*4+mm)*132 + d);
            #pragma unroll
            for (int jj = 0; jj < 4; jj++)
                k4[jj].f = *(const float4*)(Ks + (tx + 16*jj)*132 + d);
            #pragma unroll
            for (int mm = 0; mm < 4; mm++)
                #pragma unroll
                for (int jj = 0; jj < 4; jj++) {
                    ffma2(acc[mm][jj], q4[mm].u[0], k4[jj].u[0]);
                    ffma2(acc[mm][jj], q4[mm].u[1], k4[jj].u[1]);
                }
        }

        float p[4][4];
        const int kbase = t*64 + tx;
        #pragma unroll
        for (int mm = 0; mm < 4; mm++) {
            const int qrow = ty*4 + mm;
            const float* mp_ = Mb + (size_t)qrow * KV_ + kbase;
            float sv[4];
            float smax = -1e30f;
            #pragma unroll
            for (int jj = 0; jj < 4; jj++) {
                float2 u = unpack2(acc[mm][jj]);
                float s = (u.x + u.y) * SCALE_ + mp_[16*jj];
                sv[jj] = s;
                smax = fmaxf(smax, s);
            }
            #pragma unroll
            for (int o = 8; o; o >>= 1)
                smax = fmaxf(smax, __shfl_xor_sync(0xffffffffu, smax, o));
            float newm = fmaxf(mrow[mm], smax);
            float alpha = __expf(mrow[mm] - newm);
            float rsum = 0.f;
            #pragma unroll
            for (int jj = 0; jj < 4; jj++) {
                float e = __expf(sv[jj] - newm);
                p[mm][jj] = e;
                rsum += e;
            }
            #pragma unroll
            for (int o = 8; o; o >>= 1)
                rsum += __shfl_xor_sync(0xffffffffu, rsum, o);
            lrow[mm] = lrow[mm]*alpha + rsum;
            mrow[mm] = newm;
            u64 a2 = pack2(alpha, alpha);
            #pragma unroll
            for (int jj = 0; jj < 4; jj++) o2[mm][jj] = fmul2(o2[mm][jj], a2);
        }

        __syncthreads();
        #pragma unroll
        for (int mm = 0; mm < 4; mm++)
            #pragma unroll
            for (int jj = 0; jj < 4; jj++)
                Ps[(ty*4+mm)*68 + tx + 16*jj] = p[mm][jj];
        __syncthreads();

        #pragma unroll 4
        for (int n = 0; n < 64; ++n) {
            F4 v0, v1;
            v0.f = *(const float4*)(Vs + n*128 + tx*8);
            v1.f = *(const float4*)(Vs + n*128 + tx*8 + 4);
            #pragma unroll
            for (int mm = 0; mm < 4; mm++) {
                float pv = Ps[(ty*4+mm)*68 + n];
                u64 pp = pack2(pv, pv);
                ffma2(o2[mm][0], pp, v0.u[0]);
                ffma2(o2[mm][1], pp, v0.u[1]);
                ffma2(o2[mm][2], pp, v1.u[0]);
                ffma2(o2[mm][3], pp, v1.u[1]);
            }
        }
    }

    #pragma unroll
    for (int mm = 0; mm < 4; mm++) {
        float inv = 1.0f / lrow[mm];
        int qrow = qt*64 + ty*4 + mm;
        float* dstp = Out + ((size_t)b * S_ + qrow) * H_ + h*HD_ + tx*8;
        float2 r0 = unpack2(o2[mm][0]);
        float2 r1 = unpack2(o2[mm][1]);
        float2 r2 = unpack2(o2[mm][2]);
        float2 r3 = unpack2(o2[mm][3]);
        float4 w0 = make_float4(r0.x*inv, r0.y*inv, r1.x*inv, r1.y*inv);
        float4 w1 = make_float4(r2.x*inv, r2.y*inv, r3.x*inv, r3.y*inv);
        *(float4*)dstp       = w0;
        *(float4*)(dstp + 4) = w1;
    }
}

// ---------------- launch ----------------
extern "C" void kernel_launch(void* const* d_in, const int* in_sizes, int n_in,
                              void* d_out, int out_size) {
    (void)in_sizes; (void)n_in; (void)out_size;
    const float* x   = (const float*)d_in[0];
    const float* msk = (const float*)d_in[1];
    const float* kc  = (const float*)d_in[2];
    const float* vc  = (const float*)d_in[3];
    const float* Wq  = (const float*)d_in[4];
    const float* bq  = (const float*)d_in[5];
    const float* Wk  = (const float*)d_in[6];
    const float* bk  = (const float*)d_in[7];
    const float* Wv  = (const float*)d_in[8];
    const float* bv  = (const float*)d_in[9];
    const float* Wo  = (const float*)d_in[10];
    const float* bo  = (const float*)d_in[11];

    float* out = (float*)d_out;                          // [B,S,H]
    float* ko  = out + (size_t)B_ * S_ * H_;             // [B,NH,KV,HD]
    float* vo  = ko  + (size_t)B_ * NH_ * KV_ * HD_;     // [B,NH,KV,HD]

    float *gq = nullptr, *gattn = nullptr;
    cudaGetSymbolAddress((void**)&gq, g_q);
    cudaGetSymbolAddress((void**)&gattn, g_attn);
    __nv_bfloat16 *xh, *xl, *wqh, *wql, *wkh, *wkl, *wvh, *wvl, *woh, *wol;
    cudaGetSymbolAddress((void**)&xh,  sXh);  cudaGetSymbolAddress((void**)&xl,  sXl);
    cudaGetSymbolAddress((void**)&wqh, sWqh); cudaGetSymbolAddress((void**)&wql, sWql);
    cudaGetSymbolAddress((void**)&wkh, sWkh); cudaGetSymbolAddress((void**)&wkl, sWkl);
    cudaGetSymbolAddress((void**)&wvh, sWvh); cudaGetSymbolAddress((void**)&wvl, sWvl);
    cudaGetSymbolAddress((void**)&woh, sWoh); cudaGetSymbolAddress((void**)&wol, sWol);

    cudaFuncSetAttribute(attn_kernel,
                         cudaFuncAttributeMaxDynamicSharedMemorySize, ATTN_SMEM);
    cudaFuncSetAttribute(gemm_mma,
                         cudaFuncAttributeMaxDynamicSharedMemorySize, GT_SMEM);

    // 1. splice caches into output k/v
    copy_cache_kernel<<<8192, 256>>>((const float4*)kc, (const float4*)vc,
                                     (float4*)ko, (float4*)vo);

    // 2. bf16 hi/lo splits
    split_kernel<<<8192, 256>>>((const float4*)x,  (uint2*)xh,  (uint2*)xl);
    split_kernel<<<4096, 256>>>((const float4*)Wq, (uint2*)wqh, (uint2*)wql);
    split_kernel<<<4096, 256>>>((const float4*)Wk, (uint2*)wkh, (uint2*)wkl);
    split_kernel<<<4096, 256>>>((const float4*)Wv, (uint2*)wvh, (uint2*)wvl);
    split_kernel<<<4096, 256>>>((const float4*)Wo, (uint2*)woh, (uint2*)wol);

    // 3. projections on tensor cores (bf16 split, fp32 accumulate)
    dim3 ggrid(H_/128, M_/128);   // (16, 32)
    gemm_mma<<<ggrid, 256, GT_SMEM>>>(xh, xl, wqh, wql, bq, gq, 1, S_,  0);
    gemm_mma<<<ggrid, 256, GT_SMEM>>>(xh, xl, wkh, wkl, bk, ko, 1, KV_, CACHE_);
    gemm_mma<<<ggrid, 256, GT_SMEM>>>(xh, xl, wvh, wvl, bv, vo, 1, KV_, CACHE_);

    // 4. attention (fp32)
    attn_kernel<<<dim3(S_/64, NH_, B_), 256, ATTN_SMEM>>>(gq, ko, vo, msk, gattn);

    // 5. output projection (split attn output, then tensor-core GEMM)
    split_kernel<<<8192, 256>>>((const float4*)gattn, (uint2*)xh, (uint2*)xl);
    gemm_mma<<<ggrid, 256, GT_SMEM>>>(xh, xl, woh, wol, bo, out, 0, 0, 0);
}

// round 4
// speedup vs baseline: 3.2202x; 1.8910x over previous
#include <cuda_runtime.h>
#include <cuda_bf16.h>
#include <cstdint>

// ---------------- problem constants ----------------
#define B_     2
#define S_     2048
#define H_     2048
#define NH_    16
#define HD_    128
#define CACHE_ 2048
#define KV_    4096           // CACHE_ + S_
#define M_     4096           // B_*S_
#define KDIM_  2048           // H_

#define SCALE_ 0.08838834764831845f   // 1/sqrt(128)

// scratch (allocation-free rule: __device__ globals)
static __device__ float g_attn[(size_t)M_ * H_];  // attn out as [B,S,H]

// bf16 split scratch
static __device__ __nv_bfloat16 sXh[(size_t)M_ * KDIM_];
static __device__ __nv_bfloat16 sXl[(size_t)M_ * KDIM_];
static __device__ __nv_bfloat16 sWqh[(size_t)H_ * KDIM_];
static __device__ __nv_bfloat16 sWql[(size_t)H_ * KDIM_];
static __device__ __nv_bfloat16 sWkh[(size_t)H_ * KDIM_];
static __device__ __nv_bfloat16 sWkl[(size_t)H_ * KDIM_];
static __device__ __nv_bfloat16 sWvh[(size_t)H_ * KDIM_];
static __device__ __nv_bfloat16 sWvl[(size_t)H_ * KDIM_];
static __device__ __nv_bfloat16 sWoh[(size_t)H_ * KDIM_];
static __device__ __nv_bfloat16 sWol[(size_t)H_ * KDIM_];

// attention operand splits
static __device__ __nv_bfloat16 sQh[(size_t)B_ * NH_ * S_ * HD_];
static __device__ __nv_bfloat16 sQl[(size_t)B_ * NH_ * S_ * HD_];
static __device__ __nv_bfloat16 sKh[(size_t)B_ * NH_ * KV_ * HD_];
static __device__ __nv_bfloat16 sKl[(size_t)B_ * NH_ * KV_ * HD_];
static __device__ __nv_bfloat16 sVh[(size_t)B_ * NH_ * KV_ * HD_];
static __device__ __nv_bfloat16 sVl[(size_t)B_ * NH_ * KV_ * HD_];

typedef unsigned long long u64;

// ---------------- helpers ----------------
__device__ __forceinline__ uint32_t smem_u32(const void* p) {
    uint32_t a;
    asm("{ .reg .u64 t; cvta.to.shared.u64 t, %1; cvt.u32.u64 %0, t; }" : "=r"(a) : "l"(p));
    return a;
}

#define LDSM4(r0,r1,r2,r3,addr) \
    asm volatile("ldmatrix.sync.aligned.m8n8.x4.shared.b16 {%0,%1,%2,%3}, [%4];" \
        : "=r"(r0),"=r"(r1),"=r"(r2),"=r"(r3) : "r"(addr))

#define LDSM4T(r0,r1,r2,r3,addr) \
    asm volatile("ldmatrix.sync.aligned.m8n8.x4.trans.shared.b16 {%0,%1,%2,%3}, [%4];" \
        : "=r"(r0),"=r"(r1),"=r"(r2),"=r"(r3) : "r"(addr))

#define MMA16816(c, a, b) \
    asm volatile("mma.sync.aligned.m16n8k16.row.col.f32.bf16.bf16.f32 " \
        "{%0,%1,%2,%3}, {%4,%5,%6,%7}, {%8,%9}, {%0,%1,%2,%3};" \
        : "+f"((c)[0]),"+f"((c)[1]),"+f"((c)[2]),"+f"((c)[3]) \
        : "r"((a)[0]),"r"((a)[1]),"r"((a)[2]),"r"((a)[3]), "r"((b)[0]),"r"((b)[1]))

#define CP_ASYNC16(saddr, gaddr) \
    asm volatile("cp.async.cg.shared.global [%0], [%1], 16;" :: "r"(saddr), "l"(gaddr))
#define CP_COMMIT() asm volatile("cp.async.commit_group;" ::: "memory")
#define CP_WAIT0()  asm volatile("cp.async.wait_group 0;" ::: "memory")
#define CP_WAIT1()  asm volatile("cp.async.wait_group 1;" ::: "memory")

// ---------------- cache splice (+ bf16 splits) ----------------
__global__ void copy_cache_kernel(const float4* __restrict__ kc,
                                  const float4* __restrict__ vc,
                                  float4* __restrict__ ko,
                                  float4* __restrict__ vo,
                                  uint2* __restrict__ kh, uint2* __restrict__ kl,
                                  uint2* __restrict__ vh, uint2* __restrict__ vl) {
    int i = blockIdx.x * blockDim.x + threadIdx.x;
    int chunk = i >> 16;
    int rem   = i & 65535;
    size_t d = (size_t)chunk * (KV_ * HD_ / 4) + rem;
    float4 kk = kc[i];
    float4 vv = vc[i];
    ko[d] = kk;
    vo[d] = vv;
    float fk[4] = {kk.x, kk.y, kk.z, kk.w};
    float fv[4] = {vv.x, vv.y, vv.z, vv.w};
    __nv_bfloat16 khh[4], kll[4], vhh[4], vll[4];
    #pragma unroll
    for (int j = 0; j < 4; j++) {
        khh[j] = __float2bfloat16_rn(fk[j]);
        kll[j] = __float2bfloat16_rn(fk[j] - __bfloat162float(khh[j]));
        vhh[j] = __float2bfloat16_rn(fv[j]);
        vll[j] = __float2bfloat16_rn(fv[j] - __bfloat162float(vhh[j]));
    }
    kh[d] = *(uint2*)khh; kl[d] = *(uint2*)kll;
    vh[d] = *(uint2*)vhh; vl[d] = *(uint2*)vll;
}

// ---------------- fp32 -> bf16 hi/lo split ----------------
union BF4 { __nv_bfloat16 b[4]; uint2 u; };

__global__ void split_kernel(const float4* __restrict__ src,
                             uint2* __restrict__ hi, uint2* __restrict__ lo) {
    int i = blockIdx.x * blockDim.x + threadIdx.x;
    float4 v = src[i];
    BF4 H, L;
    float f[4] = {v.x, v.y, v.z, v.w};
    #pragma unroll
    for (int j = 0; j < 4; j++) {
        __nv_bfloat16 h = __float2bfloat16_rn(f[j]);
        H.b[j] = h;
        L.b[j] = __float2bfloat16_rn(f[j] - __bfloat162float(h));
    }
    hi[i] = H.u;
    lo[i] = L.u;
}

__device__ __forceinline__ void store_split(__nv_bfloat16* dh, __nv_bfloat16* dl,
                                            size_t idx, float2 v) {
    __nv_bfloat16 h0 = __float2bfloat16_rn(v.x), h1 = __float2bfloat16_rn(v.y);
    __nv_bfloat16 l0 = __float2bfloat16_rn(v.x - __bfloat162float(h0));
    __nv_bfloat16 l1 = __float2bfloat16_rn(v.y - __bfloat162float(h1));
    __nv_bfloat162 hh; hh.x = h0; hh.y = h1;
    __nv_bfloat162 ll; ll.x = l0; ll.y = l1;
    *(__nv_bfloat162*)(dh + idx) = hh;
    *(__nv_bfloat162*)(dl + idx) = ll;
}

// ---------------- mma.sync bf16-split GEMM ----------------
// mode 0: fp32 dense dst[row*H_+col]
// mode 1: fp32 scatter (KV layout) + bf16 splits to dh/dl
// mode 2: bf16 splits only (q)
#define GKC      32
#define GNCH     (KDIM_/GKC)
#define TPAD     40
#define TILE_B   (128*TPAD*2)
#define BUF_B    (4*TILE_B)
#define GT_SMEM  (512 + 2*BUF_B)

__global__ __launch_bounds__(256, 1)
void gemm_mma(const __nv_bfloat16* __restrict__ Ah, const __nv_bfloat16* __restrict__ Al,
              const __nv_bfloat16* __restrict__ Bh, const __nv_bfloat16* __restrict__ Bl,
              const float* __restrict__ bias, float* __restrict__ dst,
              __nv_bfloat16* __restrict__ dh, __nv_bfloat16* __restrict__ dl,
              int mode, int Lrow, int off)
{
    extern __shared__ char smc[];
    float* s_bias = (float*)smc;
    const uint32_t sbase = smem_u32(smc + 512);

    const int tid = threadIdx.x;
    const int wid = tid >> 5, lane = tid & 31;
    const int wm = (wid & 3) * 32, wn = (wid >> 2) * 64;
    const int n0 = blockIdx.x * 128, m0 = blockIdx.y * 128;

    if (tid < 128) s_bias[tid] = bias[n0 + tid];

    const __nv_bfloat16* tsrc[4] = {
        Ah + (size_t)m0 * KDIM_, Al + (size_t)m0 * KDIM_,
        Bh + (size_t)n0 * KDIM_, Bl + (size_t)n0 * KDIM_
    };

    const int ld_row = tid >> 2;
    const int ld_c16 = tid & 3;
    const int aRow = wm + (lane & 15);
    const uint32_t offA0 = ((uint32_t)(aRow * TPAD + ((lane >> 4) << 3))) * 2u;
    const int bRow = wn + ((lane >> 4) << 3) + (lane & 7);
    const uint32_t offB0 = ((uint32_t)(bRow * TPAD + (((lane >> 3) & 1) << 3))) * 2u;

    float acc[2][8][4];
    #pragma unroll
    for (int i = 0; i < 2; i++)
        #pragma unroll
        for (int j = 0; j < 8; j++)
            #pragma unroll
            for (int q = 0; q < 4; q++) acc[i][j][q] = 0.f;

    {
        uint32_t sb = sbase;
        #pragma unroll
        for (int t = 0; t < 4; t++) {
            const __nv_bfloat16* src = tsrc[t];
            #pragma unroll
            for (int i = 0; i < 2; i++) {
                int row = ld_row + i * 64;
                uint32_t sa = sb + t * TILE_B + (uint32_t)(row * TPAD + ld_c16 * 8) * 2u;
                const void* ga = src + (size_t)row * KDIM_ + ld_c16 * 8;
                CP_ASYNC16(sa, ga);
            }
        }
        CP_COMMIT();
    }

    for (int c = 0; c < GNCH; ++c) {
        CP_WAIT0();
        __syncthreads();
        if (c + 1 < GNCH) {
            uint32_t sb = sbase + ((c + 1) & 1) * BUF_B;
            const int c0 = (c + 1) * GKC;
            #pragma unroll
            for (int t = 0; t < 4; t++) {
                const __nv_bfloat16* src = tsrc[t] + c0;
                #pragma unroll
                for (int i = 0; i < 2; i++) {
                    int row = ld_row + i * 64;
                    uint32_t sa = sb + t * TILE_B + (uint32_t)(row * TPAD + ld_c16 * 8) * 2u;
                    const void* ga = src + (size_t)row * KDIM_ + ld_c16 * 8;
                    CP_ASYNC16(sa, ga);
                }
            }
            CP_COMMIT();
        }

        const uint32_t bb = sbase + (c & 1) * BUF_B;
        #pragma unroll
        for (int ks = 0; ks < 2; ++ks) {
            const uint32_t ko_ = ks * 32;
            uint32_t ah[2][4], al[2][4];
            #pragma unroll
            for (int mt = 0; mt < 2; ++mt) {
                LDSM4(ah[mt][0], ah[mt][1], ah[mt][2], ah[mt][3],
                      bb + 0 * TILE_B + offA0 + mt * (16 * TPAD * 2) + ko_);
                LDSM4(al[mt][0], al[mt][1], al[mt][2], al[mt][3],
                      bb + 1 * TILE_B + offA0 + mt * (16 * TPAD * 2) + ko_);
            }
            uint32_t bh[8][2], bl[8][2];
            #pragma unroll
            for (int p = 0; p < 4; ++p) {
                uint32_t r0, r1, r2, r3;
                LDSM4(r0, r1, r2, r3,
                      bb + 2 * TILE_B + offB0 + p * (16 * TPAD * 2) + ko_);
                bh[2*p][0] = r0; bh[2*p][1] = r1; bh[2*p+1][0] = r2; bh[2*p+1][1] = r3;
                LDSM4(r0, r1, r2, r3,
                      bb + 3 * TILE_B + offB0 + p * (16 * TPAD * 2) + ko_);
                bl[2*p][0] = r0; bl[2*p][1] = r1; bl[2*p+1][0] = r2; bl[2*p+1][1] = r3;
            }
            #pragma unroll
            for (int mt = 0; mt < 2; ++mt)
                #pragma unroll
                for (int nt = 0; nt < 8; ++nt) {
                    MMA16816(acc[mt][nt], ah[mt], bh[nt]);
                    MMA16816(acc[mt][nt], ah[mt], bl[nt]);
                    MMA16816(acc[mt][nt], al[mt], bh[nt]);
                }
        }
    }
    __syncthreads();

    // epilogue
    #pragma unroll
    for (int mt = 0; mt < 2; ++mt) {
        #pragma unroll
        for (int nt = 0; nt < 8; ++nt) {
            float* cc = acc[mt][nt];
            int row0 = m0 + wm + mt * 16 + (lane >> 2);
            int col  = wn + nt * 8 + (lane & 3) * 2;
            float2 v0 = make_float2(cc[0] + s_bias[col], cc[1] + s_bias[col + 1]);
            float2 v1 = make_float2(cc[2] + s_bias[col], cc[3] + s_bias[col + 1]);
            if (mode == 0) {
                float* p0 = dst + (size_t)row0 * H_ + n0 + col;
                *(float2*)p0 = v0;
                *(float2*)(p0 + (size_t)8 * H_) = v1;
            } else {
                int bb_ = row0 >> 11, s = row0 & (S_ - 1);
                int head = n0 >> 7;
                size_t idx = ((size_t)(bb_ * NH_ + head) * Lrow + off + s) * HD_ + col;
                size_t idx1 = idx + (size_t)8 * HD_;
                if (mode == 1) {
                    *(float2*)(dst + idx)  = v0;
                    *(float2*)(dst + idx1) = v1;
                }
                store_split(dh, dl, idx,  v0);
                store_split(dh, dl, idx1, v1);
            }
        }
    }
}

// ---------------- flash attention via mma.sync, bf16 3-term split ----------------
// CTA: 128 q-rows x (h,b); 8 warps, warp = m16 x (full n). KV tile 32, double-buffered.
#define AKT 32
#define QPITCH 272                     // bytes (136 bf16)
#define KOFF   0
#define LOFF   8704
#define VHOFF  17408
#define VLOFF  26112
#define MSOFF  34816
#define STAGE_B 51200                  // 4*8704 + 16384
#define QBYTES (128*QPITCH)            // 34816 per split
#define ATT_SMEM (2*QBYTES + 2*STAGE_B)  // 172032

__global__ __launch_bounds__(256, 1)
void attn_mma(const __nv_bfloat16* __restrict__ Qh, const __nv_bfloat16* __restrict__ Ql,
              const __nv_bfloat16* __restrict__ Kh, const __nv_bfloat16* __restrict__ Kl,
              const __nv_bfloat16* __restrict__ Vh, const __nv_bfloat16* __restrict__ Vl,
              const float* __restrict__ Msk,
              float* __restrict__ Out)
{
    extern __shared__ char sma[];
    const uint32_t sb = smem_u32(sma);

    const int tid = threadIdx.x;
    const int wid = tid >> 5, lane = tid & 31;
    const int qt = blockIdx.x, h = blockIdx.y, b = blockIdx.z;

    const size_t bh_q = ((size_t)(b * NH_ + h) * S_ + qt * 128) * HD_;
    const size_t bh_kv = (size_t)(b * NH_ + h) * KV_ * HD_;
    const float* Mb = Msk + ((size_t)b * S_ + qt * 128) * KV_;

    // --- Q cp.async (both splits) ---
    {
        int qr = tid >> 1, qc = (tid & 1) * 8;
        const __nv_bfloat16* qhp = Qh + bh_q + (size_t)qr * HD_ + qc * 8;
        const __nv_bfloat16* qlp = Ql + bh_q + (size_t)qr * HD_ + qc * 8;
        uint32_t d0 = sb + qr * QPITCH + qc * 16;
        #pragma unroll
        for (int j = 0; j < 8; j++) {
            CP_ASYNC16(d0 + j * 16, qhp + j * 8);
            CP_ASYNC16(d0 + QBYTES + j * 16, qlp + j * 8);
        }
    }
    // stage issue helper (macro-ish lambda)
    const int kv_row = tid >> 3, kv_c = tid & 7;
    const int m_row = tid >> 1, m_c = (tid & 1) * 4;
    auto issue_stage = [&](int t) {
        uint32_t st = sb + 2 * QBYTES + (t & 1) * STAGE_B;
        size_t go = bh_kv + (size_t)(t * AKT + kv_row) * HD_ + kv_c * 8;
        uint32_t so = st + kv_row * QPITCH + kv_c * 16;
        CP_ASYNC16(so + KOFF,        Kh + go);
        CP_ASYNC16(so + KOFF + 128,  Kh + go + 64);
        CP_ASYNC16(so + LOFF,        Kl + go);
        CP_ASYNC16(so + LOFF + 128,  Kl + go + 64);
        CP_ASYNC16(so + VHOFF,       Vh + go);
        CP_ASYNC16(so + VHOFF + 128, Vh + go + 64);
        CP_ASYNC16(so + VLOFF,       Vl + go);
        CP_ASYNC16(so + VLOFF + 128, Vl + go + 64);
        const float* mp = Mb + (size_t)m_row * KV_ + t * AKT + m_c * 4;
        uint32_t md = st + MSOFF + m_row * 128 + m_c * 16;
        #pragma unroll
        for (int j = 0; j < 4; j++)
            CP_ASYNC16(md + j * 16, mp + j * 4);
    };
    issue_stage(0);
    CP_COMMIT();

    // fragments / accumulators
    uint32_t qhF[8][4], qlF[8][4];
    float o[16][4];
    #pragma unroll
    for (int i = 0; i < 16; i++)
        #pragma unroll
        for (int j = 0; j < 4; j++) o[i][j] = 0.f;
    float m0r = -1e30f, m1r = -1e30f, l0r = 0.f, l1r = 0.f;

    const uint32_t qAoff = (uint32_t)((wid * 16 + (lane & 15)) * QPITCH + ((lane >> 4) << 3) * 2);
    const uint32_t kBrow = (uint32_t)((((lane >> 4) << 3) + (lane & 7)) * QPITCH + (((lane >> 3) & 1) << 3) * 2);
    const uint32_t vTrow = (uint32_t)(((((lane >> 3) & 1) << 3) + (lane & 7)) * QPITCH + ((lane >> 4) << 3) * 2);

    const int NIT = KV_ / AKT;   // 128
    for (int t = 0; t < NIT; ++t) {
        if (t + 1 < NIT) { issue_stage(t + 1); CP_COMMIT(); CP_WAIT1(); }
        else             { CP_WAIT0(); }
        __syncthreads();

        if (t == 0) {
            #pragma unroll
            for (int ks = 0; ks < 8; ++ks) {
                LDSM4(qhF[ks][0], qhF[ks][1], qhF[ks][2], qhF[ks][3], sb + qAoff + ks * 32);
                LDSM4(qlF[ks][0], qlF[ks][1], qlF[ks][2], qlF[ks][3], sb + QBYTES + qAoff + ks * 32);
            }
        }

        const uint32_t st = sb + 2 * QBYTES + (t & 1) * STAGE_B;

        // ---- scores: m16 x 32 ----
        float sacc[4][4];
        #pragma unroll
        for (int i = 0; i < 4; i++)
            #pragma unroll
            for (int j = 0; j < 4; j++) sacc[i][j] = 0.f;

        #pragma unroll
        for (int ks = 0; ks < 8; ++ks) {
            #pragma unroll
            for (int nh = 0; nh < 2; ++nh) {
                uint32_t kh0, kh1, kh2, kh3, kl0, kl1, kl2, kl3;
                uint32_t ka = st + KOFF + kBrow + nh * 16 * QPITCH + ks * 32;
                uint32_t la = st + LOFF + kBrow + nh * 16 * QPITCH + ks * 32;
                LDSM4(kh0, kh1, kh2, kh3, ka);
                LDSM4(kl0, kl1, kl2, kl3, la);
                uint32_t bh0[2] = {kh0, kh1}, bh1[2] = {kh2, kh3};
                uint32_t bl0[2] = {kl0, kl1}, bl1[2] = {kl2, kl3};
                MMA16816(sacc[2*nh],   qhF[ks], bh0);
                MMA16816(sacc[2*nh],   qhF[ks], bl0);
                MMA16816(sacc[2*nh],   qlF[ks], bh0);
                MMA16816(sacc[2*nh+1], qhF[ks], bh1);
                MMA16816(sacc[2*nh+1], qhF[ks], bl1);
                MMA16816(sacc[2*nh+1], qlF[ks], bh1);
            }
        }

        // ---- softmax (fp32, with mask) ----
        const uint32_t msb = st + MSOFF + (wid * 16 + (lane >> 2)) * 128 + (lane & 3) * 8;
        float p[4][4];
        float rm0 = -1e30f, rm1 = -1e30f;
        #pragma unroll
        for (int nt = 0; nt < 4; ++nt) {
            float2 mv0 = *(const float2*)(sma + (msb + nt * 32 - sb));
            float2 mv1 = *(const float2*)(sma + (msb + nt * 32 + 8 * 128 - sb));
            p[nt][0] = sacc[nt][0] * SCALE_ + mv0.x;
            p[nt][1] = sacc[nt][1] * SCALE_ + mv0.y;
            p[nt][2] = sacc[nt][2] * SCALE_ + mv1.x;
            p[nt][3] = sacc[nt][3] * SCALE_ + mv1.y;
            rm0 = fmaxf(rm0, fmaxf(p[nt][0], p[nt][1]));
            rm1 = fmaxf(rm1, fmaxf(p[nt][2], p[nt][3]));
        }
        rm0 = fmaxf(rm0, __shfl_xor_sync(0xffffffffu, rm0, 1));
        rm0 = fmaxf(rm0, __shfl_xor_sync(0xffffffffu, rm0, 2));
        rm1 = fmaxf(rm1, __shfl_xor_sync(0xffffffffu, rm1, 1));
        rm1 = fmaxf(rm1, __shfl_xor_sync(0xffffffffu, rm1, 2));
        float nm0 = fmaxf(m0r, rm0), nm1 = fmaxf(m1r, rm1);
        float al0 = __expf(m0r - nm0), al1 = __expf(m1r - nm1);
        float rs0 = 0.f, rs1 = 0.f;
        #pragma unroll
        for (int nt = 0; nt < 4; ++nt) {
            p[nt][0] = __expf(p[nt][0] - nm0);
            p[nt][1] = __expf(p[nt][1] - nm0);
            p[nt][2] = __expf(p[nt][2] - nm1);
            p[nt][3] = __expf(p[nt][3] - nm1);
            rs0 += p[nt][0] + p[nt][1];
            rs1 += p[nt][2] + p[nt][3];
        }
        rs0 += __shfl_xor_sync(0xffffffffu, rs0, 1);
        rs0 += __shfl_xor_sync(0xffffffffu, rs0, 2);
        rs1 += __shfl_xor_sync(0xffffffffu, rs1, 1);
        rs1 += __shfl_xor_sync(0xffffffffu, rs1, 2);
        l0r = l0r * al0 + rs0;
        l1r = l1r * al1 + rs1;
        m0r = nm0; m1r = nm1;
        #pragma unroll
        for (int i = 0; i < 16; i++) {
            o[i][0] *= al0; o[i][1] *= al0;
            o[i][2] *= al1; o[i][3] *= al1;
        }

        // ---- P -> bf16 hi/lo A-frags ----
        uint32_t phF[2][4], plF[2][4];
        #pragma unroll
        for (int ks2 = 0; ks2 < 2; ++ks2) {
            #pragma unroll
            for (int half = 0; half < 2; ++half) {     // which nt of the pair
                int nt = 2 * ks2 + half;
                #pragma unroll
                for (int rr = 0; rr < 2; ++rr) {       // row r / r+8 (c01 / c23)
                    float f0 = p[nt][2*rr], f1 = p[nt][2*rr+1];
                    __nv_bfloat16 h0 = __float2bfloat16_rn(f0);
                    __nv_bfloat16 h1 = __float2bfloat16_rn(f1);
                    __nv_bfloat16 g0 = __float2bfloat16_rn(f0 - __bfloat162float(h0));
                    __nv_bfloat16 g1 = __float2bfloat16_rn(f1 - __bfloat162float(h1));
                    __nv_bfloat162 hp; hp.x = h0; hp.y = h1;
                    __nv_bfloat162 lp; lp.x = g0; lp.y = g1;
                    phF[ks2][half*2 + rr] = *(uint32_t*)&hp;
                    plF[ks2][half*2 + rr] = *(uint32_t*)&lp;
                }
            }
        }

        // ---- PV: o[m16][128] += P[m16][32] * V[32][128] ----
        #pragma unroll
        for (int ks2 = 0; ks2 < 2; ++ks2) {
            #pragma unroll
            for (int vb = 0; vb < 8; ++vb) {
                uint32_t h0, h1, h2, h3, g0, g1, g2, g3;
                uint32_t va = st + VHOFF + vTrow + ks2 * 16 * QPITCH + vb * 32;
                uint32_t wa = st + VLOFF + vTrow + ks2 * 16 * QPITCH + vb * 32;
                LDSM4T(h0, h1, h2, h3, va);
                LDSM4T(g0, g1, g2, g3, wa);
                uint32_t bh0[2] = {h0, h1}, bh1[2] = {h2, h3};
                uint32_t bl0[2] = {g0, g1}, bl1[2] = {g2, g3};
                MMA16816(o[2*vb],   phF[ks2], bh0);
                MMA16816(o[2*vb],   phF[ks2], bl0);
                MMA16816(o[2*vb],   plF[ks2], bh0);
                MMA16816(o[2*vb+1], phF[ks2], bh1);
                MMA16816(o[2*vb+1], phF[ks2], bl1);
                MMA16816(o[2*vb+1], plF[ks2], bh1);
            }
        }
        __syncthreads();
    }

    // ---- epilogue ----
    float i0 = 1.0f / l0r, i1 = 1.0f / l1r;
    int r0 = qt * 128 + wid * 16 + (lane >> 2);
    float* base0 = Out + ((size_t)b * S_ + r0) * H_ + h * HD_ + (lane & 3) * 2;
    float* base1 = base0 + (size_t)8 * H_;
    #pragma unroll
    for (int nt = 0; nt < 16; ++nt) {
        *(float2*)(base0 + nt * 8) = make_float2(o[nt][0] * i0, o[nt][1] * i0);
        *(float2*)(base1 + nt * 8) = make_float2(o[nt][2] * i1, o[nt][3] * i1);
    }
}

// ---------------- launch ----------------
extern "C" void kernel_launch(void* const* d_in, const int* in_sizes, int n_in,
                              void* d_out, int out_size) {
    (void)in_sizes; (void)n_in; (void)out_size;
    const float* x   = (const float*)d_in[0];
    const float* msk = (const float*)d_in[1];
    const float* kc  = (const float*)d_in[2];
    const float* vc  = (const float*)d_in[3];
    const float* Wq  = (const float*)d_in[4];
    const float* bq  = (const float*)d_in[5];
    const float* Wk  = (const float*)d_in[6];
    const float* bk  = (const float*)d_in[7];
    const float* Wv  = (const float*)d_in[8];
    const float* bv  = (const float*)d_in[9];
    const float* Wo  = (const float*)d_in[10];
    const float* bo  = (const float*)d_in[11];

    float* out = (float*)d_out;
    float* ko  = out + (size_t)B_ * S_ * H_;
    float* vo  = ko  + (size_t)B_ * NH_ * KV_ * HD_;

    float* gattn = nullptr;
    cudaGetSymbolAddress((void**)&gattn, g_attn);
    __nv_bfloat16 *xh, *xl, *wqh, *wql, *wkh, *wkl, *wvh, *wvl, *woh, *wol;
    __nv_bfloat16 *qh, *ql, *kh, *kl, *vh, *vl;
    cudaGetSymbolAddress((void**)&xh,  sXh);  cudaGetSymbolAddress((void**)&xl,  sXl);
    cudaGetSymbolAddress((void**)&wqh, sWqh); cudaGetSymbolAddress((void**)&wql, sWql);
    cudaGetSymbolAddress((void**)&wkh, sWkh); cudaGetSymbolAddress((void**)&wkl, sWkl);
    cudaGetSymbolAddress((void**)&wvh, sWvh); cudaGetSymbolAddress((void**)&wvl, sWvl);
    cudaGetSymbolAddress((void**)&woh, sWoh); cudaGetSymbolAddress((void**)&wol, sWol);
    cudaGetSymbolAddress((void**)&qh, sQh); cudaGetSymbolAddress((void**)&ql, sQl);
    cudaGetSymbolAddress((void**)&kh, sKh); cudaGetSymbolAddress((void**)&kl, sKl);
    cudaGetSymbolAddress((void**)&vh, sVh); cudaGetSymbolAddress((void**)&vl, sVl);

    cudaFuncSetAttribute(gemm_mma,
                         cudaFuncAttributeMaxDynamicSharedMemorySize, GT_SMEM);
    cudaFuncSetAttribute(attn_mma,
                         cudaFuncAttributeMaxDynamicSharedMemorySize, ATT_SMEM);

    // 1. splice caches into output k/v (+ splits for attention)
    copy_cache_kernel<<<8192, 256>>>((const float4*)kc, (const float4*)vc,
                                     (float4*)ko, (float4*)vo,
                                     (uint2*)kh, (uint2*)kl, (uint2*)vh, (uint2*)vl);

    // 2. bf16 hi/lo splits of inputs
    split_kernel<<<8192, 256>>>((const float4*)x,  (uint2*)xh,  (uint2*)xl);
    split_kernel<<<4096, 256>>>((const float4*)Wq, (uint2*)wqh, (uint2*)wql);
    split_kernel<<<4096, 256>>>((const float4*)Wk, (uint2*)wkh, (uint2*)wkl);
    split_kernel<<<4096, 256>>>((const float4*)Wv, (uint2*)wvh, (uint2*)wvl);
    split_kernel<<<4096, 256>>>((const float4*)Wo, (uint2*)woh, (uint2*)wol);

    // 3. projections (tensor cores); epilogues emit bf16 splits for attention
    dim3 ggrid(H_/128, M_/128);
    gemm_mma<<<ggrid, 256, GT_SMEM>>>(xh, xl, wqh, wql, bq, nullptr, qh, ql, 2, S_,  0);
    gemm_mma<<<ggrid, 256, GT_SMEM>>>(xh, xl, wkh, wkl, bk, ko, kh, kl, 1, KV_, CACHE_);
    gemm_mma<<<ggrid, 256, GT_SMEM>>>(xh, xl, wvh, wvl, bv, vo, vh, vl, 1, KV_, CACHE_);

    // 4. attention (tensor cores, 3-term bf16 split)
    attn_mma<<<dim3(S_/128, NH_, B_), 256, ATT_SMEM>>>(qh, ql, kh, kl, vh, vl, msk, gattn);

    // 5. output projection
    split_kernel<<<8192, 256>>>((const float4*)gattn, (uint2*)xh, (uint2*)xl);
    gemm_mma<<<ggrid, 256, GT_SMEM>>>(xh, xl, woh, wol, bo, out, nullptr, nullptr, 0, 0, 0);
}